// round 10
// baseline (speedup 1.0000x reference)
#include <cuda_runtime.h>
#include <cuda_bf16.h>
#include <cstdint>
#include <math.h>

#define MAXM 100000
#define MPAD 100096          // 782*128, covers last GEMM tile rows
#define CAP  4096

// ---------------- scratch (device globals; no allocations allowed) ----------
__device__ int   g_cnt[27];
__device__ int   g_pairM[27 * CAP];
__device__ int   g_pairS[27 * CAP];
// fp32 scratch: t1(M*128) t2(M*128) qa(M*64) qd(M*256) = M*576 floats
__device__ float g_buf[(size_t)MAXM * 576];
// bf16 [hi|lo] activation buffers (conv chain: act0/act1 ; cond chain: act2/act3)
__device__ __nv_bfloat16 g_act0[(size_t)MPAD * 512];
__device__ __nv_bfloat16 g_act1[(size_t)MPAD * 512];
__device__ __nv_bfloat16 g_act2[(size_t)MPAD * 512];
__device__ __nv_bfloat16 g_act3[(size_t)MPAD * 512];
// bf16 [hi|lo] transposed 27-tap conv weights: [27][N=128][2K=256] per conv
__device__ __nv_bfloat16 g_w27[4 * 27 * 32768];
#define W27_1A 0
#define W27_1B (27 * 32768)
#define W27_2A (2 * 27 * 32768)
#define W27_2B (3 * 27 * 32768)
// bf16 [hi|lo] transposed MLP weights [N][2K]
__device__ __nv_bfloat16 g_wt[16384 + 65536 + 131072];
#define OFF_WQ2 0
#define OFF_WQ3 16384
#define OFF_WQ4 (16384 + 65536)

__device__ __forceinline__ uint32_t smem_to_u32(const void* p) {
    uint32_t a;
    asm("{ .reg .u64 t; cvta.to.shared.u64 t, %1; cvt.u32.u64 %0, t; }" : "=r"(a) : "l"(p));
    return a;
}
__device__ __forceinline__ uint32_t sw128(uint32_t b) { return b ^ ((b >> 3) & 0x70); }

// ---------------- neighbor compaction ---------------------------------------
__global__ void zero_cnt_kernel() {
    if (threadIdx.x < 27) g_cnt[threadIdx.x] = 0;
}
__global__ void compact_kernel(const int* __restrict__ nbr, int Mrows) {
    int idx = blockIdx.x * blockDim.x + threadIdx.x;
    if (idx >= 27 * Mrows) return;
    int k = idx / Mrows;
    if (k == 13) return;
    int s = nbr[idx];
    if (s >= 0) {
        int m = idx - k * Mrows;
        int pos = atomicAdd(&g_cnt[k], 1);
        if (pos < CAP) { g_pairM[k * CAP + pos] = m; g_pairS[k * CAP + pos] = s; }
    }
}

// ---------------- fp32 -> bf16 hi/lo conversions -----------------------------
__device__ __forceinline__ void split_bf16(float v, __nv_bfloat16& h, __nv_bfloat16& l) {
    h = __float2bfloat16(v);
    l = __float2bfloat16(v - __bfloat162float(h));
}
template <bool RELU>
__global__ void convert_act_kernel(const float* __restrict__ src,
                                   __nv_bfloat16* __restrict__ dst, int Mrows, int K) {
    int idx = blockIdx.x * blockDim.x + threadIdx.x;
    int total = Mrows * (K / 4);
    if (idx >= total) return;
    int m  = idx / (K / 4);
    int k4 = (idx % (K / 4)) * 4;
    float4 v = *reinterpret_cast<const float4*>(src + (size_t)m * K + k4);
    if (RELU) {
        v.x = fmaxf(v.x, 0.f); v.y = fmaxf(v.y, 0.f);
        v.z = fmaxf(v.z, 0.f); v.w = fmaxf(v.w, 0.f);
    }
    __nv_bfloat16 h[4], l[4];
    split_bf16(v.x, h[0], l[0]); split_bf16(v.y, h[1], l[1]);
    split_bf16(v.z, h[2], l[2]); split_bf16(v.w, h[3], l[3]);
    __nv_bfloat16* dh = dst + (size_t)m * 2 * K + k4;
    *reinterpret_cast<__nv_bfloat162*>(dh)     = __nv_bfloat162(h[0], h[1]);
    *reinterpret_cast<__nv_bfloat162*>(dh + 2) = __nv_bfloat162(h[2], h[3]);
    __nv_bfloat16* dl = dh + K;
    *reinterpret_cast<__nv_bfloat162*>(dl)     = __nv_bfloat162(l[0], l[1]);
    *reinterpret_cast<__nv_bfloat162*>(dl + 2) = __nv_bfloat162(l[2], l[3]);
}
// W [K,N] fp32 -> dst [N][2K] bf16 (hi | lo), transposed
__global__ void convert_w_kernel(const float* __restrict__ W,
                                 __nv_bfloat16* __restrict__ dst, int K, int N) {
    int idx = blockIdx.x * blockDim.x + threadIdx.x;
    if (idx >= K * N) return;
    int k = idx / N, n = idx % N;
    __nv_bfloat16 h, l;
    split_bf16(W[idx], h, l);
    dst[(size_t)n * 2 * K + k]     = h;
    dst[(size_t)n * 2 * K + K + k] = l;
}
// all 27 taps of all 4 convs in one kernel
__global__ void convert_w27x4_kernel(const float* __restrict__ Wa, const float* __restrict__ Wb,
                                     const float* __restrict__ Wc, const float* __restrict__ Wd,
                                     __nv_bfloat16* __restrict__ dst) {
    int idx = blockIdx.x * blockDim.x + threadIdx.x;
    if (idx >= 4 * 27 * 16384) return;
    int conv = idx / (27 * 16384);
    int rem  = idx % (27 * 16384);
    const float* W = (conv == 0) ? Wa : (conv == 1) ? Wb : (conv == 2) ? Wc : Wd;
    int k = rem >> 14;
    int r = (rem >> 7) & 127;   // K index
    int n = rem & 127;          // N index
    __nv_bfloat16 h, l;
    split_bf16(W[rem], h, l);
    __nv_bfloat16* d = dst + (size_t)conv * 27 * 32768 + (size_t)k * 32768 + n * 256;
    d[r]       = h;
    d[128 + r] = l;
}
// FiLM + conversion: dst = bf16 split of (t2*beta+gamma), K=128
__global__ void film_convert_kernel(const float* __restrict__ t2, const float* __restrict__ qd,
                                    __nv_bfloat16* __restrict__ dst, int Mrows) {
    int idx = blockIdx.x * blockDim.x + threadIdx.x;
    if (idx >= Mrows * 32) return;
    int m  = idx / 32;
    int c4 = (idx % 32) * 4;
    float4 t = *reinterpret_cast<const float4*>(t2 + (size_t)m * 128 + c4);
    float4 b = *reinterpret_cast<const float4*>(qd + (size_t)m * 256 + c4);
    float4 g = *reinterpret_cast<const float4*>(qd + (size_t)m * 256 + 128 + c4);
    float4 o;
    o.x = fmaf(t.x, b.x, g.x); o.y = fmaf(t.y, b.y, g.y);
    o.z = fmaf(t.z, b.z, g.z); o.w = fmaf(t.w, b.w, g.w);
    __nv_bfloat16 h[4], l[4];
    split_bf16(o.x, h[0], l[0]); split_bf16(o.y, h[1], l[1]);
    split_bf16(o.z, h[2], l[2]); split_bf16(o.w, h[3], l[3]);
    __nv_bfloat16* dh = dst + (size_t)m * 256 + c4;
    *reinterpret_cast<__nv_bfloat162*>(dh)     = __nv_bfloat162(h[0], h[1]);
    *reinterpret_cast<__nv_bfloat162*>(dh + 2) = __nv_bfloat162(h[2], h[3]);
    __nv_bfloat16* dl = dh + 128;
    *reinterpret_cast<__nv_bfloat162*>(dl)     = __nv_bfloat162(l[0], l[1]);
    *reinterpret_cast<__nv_bfloat162*>(dl + 2) = __nv_bfloat162(l[2], l[3]);
}

// ================= mma.sync primitives =======================================
#define SMEM_BYTES 65536   // 2 stages x (16KB A + 16KB B)

__device__ __forceinline__ void cp_async16(uint32_t dst, const void* src) {
    asm volatile("cp.async.cg.shared.global [%0], [%1], 16;" :: "r"(dst), "l"(src));
}
__device__ __forceinline__ void cp_commit() {
    asm volatile("cp.async.commit_group;");
}
__device__ __forceinline__ void ldm_x4(uint32_t a, uint32_t& r0, uint32_t& r1,
                                       uint32_t& r2, uint32_t& r3) {
    asm volatile("ldmatrix.sync.aligned.m8n8.x4.shared.b16 {%0,%1,%2,%3}, [%4];"
                 : "=r"(r0), "=r"(r1), "=r"(r2), "=r"(r3) : "r"(a));
}
__device__ __forceinline__ void mma16816(float* c, const uint32_t* a, const uint32_t* b) {
    asm volatile("mma.sync.aligned.m16n8k16.row.col.f32.bf16.bf16.f32 "
                 "{%0,%1,%2,%3}, {%4,%5,%6,%7}, {%8,%9}, {%0,%1,%2,%3};"
                 : "+f"(c[0]), "+f"(c[1]), "+f"(c[2]), "+f"(c[3])
                 : "r"(a[0]), "r"(a[1]), "r"(a[2]), "r"(a[3]), "r"(b[0]), "r"(b[1]));
}

// ================= dense GEMM: 128x128 tile, 4 warps x 64x64, 3-pass split ===
template <bool RELU_OUT, bool RESID, bool WF32, bool WBF16>
__global__ void __launch_bounds__(128, 2)
mma_gemm_kernel(const __nv_bfloat16* __restrict__ Act,
                const __nv_bfloat16* __restrict__ Wt,
                const float* __restrict__ bias, const float* __restrict__ resid,
                float* __restrict__ C, __nv_bfloat16* __restrict__ ActOut,
                int Mrows, int K, int Ntot)
{
    extern __shared__ __align__(1024) char smem[];
    const uint32_t sbase = smem_to_u32(smem);

    const int tid  = threadIdx.x;
    const int lane = tid & 31;
    const int wid  = tid >> 5;          // 0..3
    const int wm   = wid >> 1;          // 0..1 (64-row slab)
    const int wn   = wid & 1;           // 0..1 (64-col slab)
    const int row0 = blockIdx.x * 128;
    const int n0   = blockIdx.y * 128;
    const size_t strideA = 2 * (size_t)K;

    float acc[4][8][4];
#pragma unroll
    for (int mi = 0; mi < 4; mi++)
#pragma unroll
        for (int ni = 0; ni < 8; ni++)
#pragma unroll
            for (int j = 0; j < 4; j++) acc[mi][ni][j] = 0.f;

    const int kc64 = K / 64;
    const int nch  = 3 * kc64;

    auto load_stage = [&](int c, int stage) {
        const int seg = c / kc64;
        const int kk  = (c % kc64) * 64;
        const int Ak  = kk + (seg == 1 ? K : 0);
        const int Bk  = kk + (seg == 2 ? K : 0);
        const uint32_t sA = sbase + stage * 32768u;
        const uint32_t sB = sA + 16384u;
#pragma unroll
        for (int it = 0; it < 8; it++) {
            int i  = tid + it * 128;          // 0..1023
            int r  = i >> 3;
            int c16 = i & 7;
            cp_async16(sA + sw128(r * 128 + c16 * 16),
                       Act + (size_t)(row0 + r) * strideA + Ak + c16 * 8);
            cp_async16(sB + sw128(r * 128 + c16 * 16),
                       Wt + (size_t)(n0 + r) * strideA + Bk + c16 * 8);
        }
        cp_commit();
    };

    load_stage(0, 0);
    for (int c = 0; c < nch; c++) {
        const int cur = c & 1;
        const bool more = (c + 1 < nch);
        if (more) load_stage(c + 1, cur ^ 1);
        if (more) asm volatile("cp.async.wait_group 1;");
        else      asm volatile("cp.async.wait_group 0;");
        __syncthreads();

        const uint32_t sA = sbase + cur * 32768u;
        const uint32_t sB = sA + 16384u;
#pragma unroll
        for (int kk = 0; kk < 4; kk++) {
            uint32_t af[4][4];
#pragma unroll
            for (int mi = 0; mi < 4; mi++) {
                int r = wm * 64 + mi * 16 + (lane & 15);
                uint32_t a = sA + sw128((uint32_t)(r * 128 + kk * 32 + (lane >> 4) * 16));
                ldm_x4(a, af[mi][0], af[mi][1], af[mi][2], af[mi][3]);
            }
            uint32_t bf[8][2];
#pragma unroll
            for (int nj = 0; nj < 4; nj++) {
                int g = lane >> 3;
                int nr = wn * 64 + nj * 16 + (g >> 1) * 8 + (lane & 7);
                uint32_t a = sB + sw128((uint32_t)(nr * 128 + kk * 32 + (g & 1) * 16));
                uint32_t r0, r1, r2, r3;
                ldm_x4(a, r0, r1, r2, r3);
                bf[nj * 2][0] = r0; bf[nj * 2][1] = r1;
                bf[nj * 2 + 1][0] = r2; bf[nj * 2 + 1][1] = r3;
            }
#pragma unroll
            for (int mi = 0; mi < 4; mi++)
#pragma unroll
                for (int ni = 0; ni < 8; ni++)
                    mma16816(acc[mi][ni], af[mi], bf[ni]);
        }
        __syncthreads();
    }

    const int tg  = lane >> 2;
    const int tc2 = (lane & 3) * 2;
#pragma unroll
    for (int mi = 0; mi < 4; mi++) {
#pragma unroll
        for (int half = 0; half < 2; half++) {
            const int gr = row0 + wm * 64 + mi * 16 + tg + half * 8;
            if (gr >= Mrows) continue;
#pragma unroll
            for (int ni = 0; ni < 8; ni++) {
                const int gc = n0 + wn * 64 + ni * 8 + tc2;
                float2 o;
                o.x = acc[mi][ni][half * 2 + 0];
                o.y = acc[mi][ni][half * 2 + 1];
                float2 bv = *reinterpret_cast<const float2*>(bias + gc);
                o.x += bv.x; o.y += bv.y;
                if (RESID) {
                    float2 rv = *reinterpret_cast<const float2*>(resid + (size_t)gr * Ntot + gc);
                    o.x += rv.x; o.y += rv.y;
                }
                if (RELU_OUT) { o.x = fmaxf(o.x, 0.f); o.y = fmaxf(o.y, 0.f); }
                if (WF32)
                    *reinterpret_cast<float2*>(C + (size_t)gr * Ntot + gc) = o;
                if (WBF16) {
                    __nv_bfloat16 h0, l0, h1, l1;
                    split_bf16(o.x, h0, l0);
                    split_bf16(o.y, h1, l1);
                    *reinterpret_cast<__nv_bfloat162*>(ActOut + (size_t)gr * 2 * Ntot + gc)
                        = __nv_bfloat162(h0, h1);
                    *reinterpret_cast<__nv_bfloat162*>(ActOut + (size_t)gr * 2 * Ntot + Ntot + gc)
                        = __nv_bfloat162(l0, l1);
                }
            }
        }
    }
}

// ============ MMA scatter: Out[dst[p]] += Act[src[p]] @ W27[k]^T =============
// 4 warps x 64x64 warp tiles (same shape as the dense GEMM), occ 2
__global__ void __launch_bounds__(128, 2)
scatter_mma_kernel(const __nv_bfloat16* __restrict__ Act,
                   const __nv_bfloat16* __restrict__ W27,
                   float* __restrict__ Out)
{
    extern __shared__ __align__(1024) char smem[];
    __shared__ int srow[128];
    __shared__ int drow[128];
    const uint32_t sbase = smem_to_u32(smem);

    int kk = blockIdx.y;
    if (kk >= 13) kk++;
    const int cnt = g_cnt[kk];
    const int p0  = blockIdx.x * 128;
    if (p0 >= cnt) return;
    const int np = min(128, cnt - p0);

    const int tid  = threadIdx.x;
    const int lane = tid & 31;
    const int wid  = tid >> 5;          // 0..3
    const int wm   = wid >> 1;          // 0..1
    const int wn   = wid & 1;           // 0..1

    {
        int p = p0 + min(tid, np - 1);
        srow[tid] = g_pairS[kk * CAP + p];
        drow[tid] = (tid < np) ? g_pairM[kk * CAP + p] : -1;
    }
    __syncthreads();

    const __nv_bfloat16* Wt = W27 + (size_t)kk * 32768;

    float acc[4][8][4];
#pragma unroll
    for (int mi = 0; mi < 4; mi++)
#pragma unroll
        for (int ni = 0; ni < 8; ni++)
#pragma unroll
            for (int j = 0; j < 4; j++) acc[mi][ni][j] = 0.f;

    auto load_stage = [&](int c, int stage) {
        const int seg = c >> 1;
        const int kk64 = (c & 1) * 64;
        const int Ak  = kk64 + (seg == 1 ? 128 : 0);
        const int Bk  = kk64 + (seg == 2 ? 128 : 0);
        const uint32_t sA = sbase + stage * 32768u;
        const uint32_t sB = sA + 16384u;
#pragma unroll
        for (int it = 0; it < 8; it++) {
            int i  = tid + it * 128;
            int r  = i >> 3;
            int c16 = i & 7;
            cp_async16(sA + sw128(r * 128 + c16 * 16),
                       Act + (size_t)srow[r] * 256 + Ak + c16 * 8);
            cp_async16(sB + sw128(r * 128 + c16 * 16),
                       Wt + (size_t)r * 256 + Bk + c16 * 8);
        }
        cp_commit();
    };

    load_stage(0, 0);
    for (int c = 0; c < 6; c++) {
        const int cur = c & 1;
        const bool more = (c + 1 < 6);
        if (more) load_stage(c + 1, cur ^ 1);
        if (more) asm volatile("cp.async.wait_group 1;");
        else      asm volatile("cp.async.wait_group 0;");
        __syncthreads();

        const uint32_t sA = sbase + cur * 32768u;
        const uint32_t sB = sA + 16384u;
#pragma unroll
        for (int kq = 0; kq < 4; kq++) {
            uint32_t af[4][4];
#pragma unroll
            for (int mi = 0; mi < 4; mi++) {
                int r = wm * 64 + mi * 16 + (lane & 15);
                uint32_t a = sA + sw128((uint32_t)(r * 128 + kq * 32 + (lane >> 4) * 16));
                ldm_x4(a, af[mi][0], af[mi][1], af[mi][2], af[mi][3]);
            }
            uint32_t bf[8][2];
#pragma unroll
            for (int nj = 0; nj < 4; nj++) {
                int g = lane >> 3;
                int nr = wn * 64 + nj * 16 + (g >> 1) * 8 + (lane & 7);
                uint32_t a = sB + sw128((uint32_t)(nr * 128 + kq * 32 + (g & 1) * 16));
                uint32_t r0, r1, r2, r3;
                ldm_x4(a, r0, r1, r2, r3);
                bf[nj * 2][0] = r0; bf[nj * 2][1] = r1;
                bf[nj * 2 + 1][0] = r2; bf[nj * 2 + 1][1] = r3;
            }
#pragma unroll
            for (int mi = 0; mi < 4; mi++)
#pragma unroll
                for (int ni = 0; ni < 8; ni++)
                    mma16816(acc[mi][ni], af[mi], bf[ni]);
        }
        __syncthreads();
    }

    const int tg  = lane >> 2;
    const int tc2 = (lane & 3) * 2;
#pragma unroll
    for (int mi = 0; mi < 4; mi++) {
#pragma unroll
        for (int half = 0; half < 2; half++) {
            const int rl = wm * 64 + mi * 16 + tg + half * 8;
            const int gr = drow[rl];
            if (gr < 0) continue;
            float* Orow = Out + (size_t)gr * 128;
#pragma unroll
            for (int ni = 0; ni < 8; ni++) {
                const int gc = wn * 64 + ni * 8 + tc2;
                atomicAdd(Orow + gc,     acc[mi][ni][half * 2 + 0]);
                atomicAdd(Orow + gc + 1, acc[mi][ni][half * 2 + 1]);
            }
        }
    }
}

// ---------------- SIMT GEMM (tiny K=16 cond conv) ----------------------------
template <int BM, int BN, int BK, int TM, int TN, bool RELU_A, bool RELU_OUT, bool RESID>
__global__ void __launch_bounds__((BM / TM) * (BN / TN))
gemm_kernel(const float* __restrict__ A, const float* __restrict__ B,
            const float* __restrict__ bias, const float* __restrict__ resid,
            float* __restrict__ C, int Mrows, int Kdim, int Ndim)
{
    constexpr int NT = (BM / TM) * (BN / TN);
    __shared__ float As[BK][BM];
    __shared__ float Bs[BK][BN];
    const int tid  = threadIdx.x;
    const int row0 = blockIdx.x * BM;
    const int col0 = blockIdx.y * BN;
    const int tr   = tid / (BN / TN);
    const int tc   = tid % (BN / TN);
    float acc[TM][TN];
#pragma unroll
    for (int i = 0; i < TM; i++)
#pragma unroll
        for (int j = 0; j < TN; j++) acc[i][j] = 0.f;
    for (int k0 = 0; k0 < Kdim; k0 += BK) {
        for (int i = tid * 4; i < BM * BK; i += NT * 4) {
            int r = i / BK, kk = i % BK;
            float4 v = make_float4(0.f, 0.f, 0.f, 0.f);
            int grr = row0 + r;
            if (grr < Mrows)
                v = *reinterpret_cast<const float4*>(A + (size_t)grr * Kdim + k0 + kk);
            if (RELU_A) {
                v.x = fmaxf(v.x, 0.f); v.y = fmaxf(v.y, 0.f);
                v.z = fmaxf(v.z, 0.f); v.w = fmaxf(v.w, 0.f);
            }
            As[kk + 0][r] = v.x; As[kk + 1][r] = v.y;
            As[kk + 2][r] = v.z; As[kk + 3][r] = v.w;
        }
        for (int i = tid * 4; i < BK * BN; i += NT * 4) {
            int r = i / BN, c = i % BN;
            *reinterpret_cast<float4*>(&Bs[r][c]) =
                *reinterpret_cast<const float4*>(B + (size_t)(k0 + r) * Ndim + col0 + c);
        }
        __syncthreads();
#pragma unroll
        for (int kk = 0; kk < BK; kk++) {
            float af[TM], bf2[TN];
#pragma unroll
            for (int i = 0; i < TM; i++) af[i] = As[kk][tr * TM + i];
#pragma unroll
            for (int j = 0; j < TN; j++) bf2[j] = Bs[kk][tc * TN + j];
#pragma unroll
            for (int i = 0; i < TM; i++)
#pragma unroll
                for (int j = 0; j < TN; j++) acc[i][j] = fmaf(af[i], bf2[j], acc[i][j]);
        }
        __syncthreads();
    }
#pragma unroll
    for (int i = 0; i < TM; i++) {
        int grr = row0 + tr * TM + i;
        if (grr >= Mrows) continue;
        float* Crow = C + (size_t)grr * Ndim + col0 + tc * TN;
#pragma unroll
        for (int j = 0; j < TN; j += 4) {
            int gc = col0 + tc * TN + j;
            float4 bv = *reinterpret_cast<const float4*>(bias + gc);
            float4 o;
            o.x = acc[i][j + 0] + bv.x; o.y = acc[i][j + 1] + bv.y;
            o.z = acc[i][j + 2] + bv.z; o.w = acc[i][j + 3] + bv.w;
            if (RESID) {
                float4 rv = *reinterpret_cast<const float4*>(resid + (size_t)grr * Ndim + gc);
                o.x += rv.x; o.y += rv.y; o.z += rv.z; o.w += rv.w;
            }
            if (RELU_OUT) {
                o.x = fmaxf(o.x, 0.f); o.y = fmaxf(o.y, 0.f);
                o.z = fmaxf(o.z, 0.f); o.w = fmaxf(o.w, 0.f);
            }
            *reinterpret_cast<float4*>(Crow + j) = o;
        }
    }
}

// ---------------- SIMT scatter (tiny cond conv taps, Ci=16) ------------------
template <int Ci, int Co, int PB, bool RELU_A>
__global__ void __launch_bounds__(Co)
scatter_kernel(const float* __restrict__ F, const float* __restrict__ W,
               float* __restrict__ Out)
{
    int kk = blockIdx.y;
    if (kk >= 13) kk++;
    const int cnt = g_cnt[kk];
    const int p0  = blockIdx.x * PB;
    if (p0 >= cnt) return;
    const int np = min(PB, cnt - p0);
    __shared__ float gsh[PB][Ci];
    __shared__ int   mout[PB];
    const int tid = threadIdx.x;
    for (int i = tid; i < PB * Ci; i += Co) {
        int p = i / Ci, c = i % Ci;
        float v = 0.f;
        if (p < np) {
            int ms = g_pairS[kk * CAP + p0 + p];
            v = F[(size_t)ms * Ci + c];
            if (RELU_A) v = fmaxf(v, 0.f);
        }
        gsh[p][c] = v;
    }
    if (tid < PB) mout[tid] = (tid < np) ? g_pairM[kk * CAP + p0 + tid] : 0;
    __syncthreads();
    float acc[PB];
#pragma unroll
    for (int p = 0; p < PB; p++) acc[p] = 0.f;
    const float* Wk = W + (size_t)kk * Ci * Co + tid;
#pragma unroll 4
    for (int i = 0; i < Ci; i++) {
        float wv = Wk[(size_t)i * Co];
#pragma unroll
        for (int p = 0; p < PB; p++) acc[p] = fmaf(gsh[p][i], wv, acc[p]);
    }
    for (int p = 0; p < np; p++)
        atomicAdd(&Out[(size_t)mout[p] * Co + tid], acc[p]);
}

// ---------------- launch -----------------------------------------------------
extern "C" void kernel_launch(void* const* d_in, const int* in_sizes, int n_in,
                              void* d_out, int out_size)
{
    const float* x    = (const float*)d_in[0];
    const float* cond = (const float*)d_in[1];
    const float* W1a  = (const float*)d_in[2];   const float* b1a = (const float*)d_in[3];
    const float* W1b  = (const float*)d_in[4];   const float* b1b = (const float*)d_in[5];
    const float* W2a  = (const float*)d_in[6];   const float* b2a = (const float*)d_in[7];
    const float* W2b  = (const float*)d_in[8];   const float* b2b = (const float*)d_in[9];
    const float* WQ1  = (const float*)d_in[10];  const float* bQ1 = (const float*)d_in[11];
    const float* WQ2  = (const float*)d_in[12];  const float* bQ2 = (const float*)d_in[13];
    const float* WQ3  = (const float*)d_in[14];  const float* bQ3 = (const float*)d_in[15];
    const float* WQ4  = (const float*)d_in[16];  const float* bQ4 = (const float*)d_in[17];
    const int*   nbr  = (const int*)d_in[18];
    float* out = (float*)d_out;

    const int M = in_sizes[0] / 128;

    float* buf = nullptr;           cudaGetSymbolAddress((void**)&buf, g_buf);
    __nv_bfloat16* act0 = nullptr;  cudaGetSymbolAddress((void**)&act0, g_act0);
    __nv_bfloat16* act1 = nullptr;  cudaGetSymbolAddress((void**)&act1, g_act1);
    __nv_bfloat16* act2 = nullptr;  cudaGetSymbolAddress((void**)&act2, g_act2);
    __nv_bfloat16* act3 = nullptr;  cudaGetSymbolAddress((void**)&act3, g_act3);
    __nv_bfloat16* w27 = nullptr;   cudaGetSymbolAddress((void**)&w27, g_w27);
    __nv_bfloat16* wt = nullptr;    cudaGetSymbolAddress((void**)&wt, g_wt);

    float* t1 = buf;                            // M*128
    float* t2 = t1 + (size_t)MAXM * 128;        // M*128
    float* qa = t2 + (size_t)MAXM * 128;        // M*64
    float* qd = qa + (size_t)MAXM * 64;         // M*256

    // static fork/join machinery (created on first, non-capture call)
    static cudaStream_t sQ = nullptr;
    static cudaEvent_t evFork = nullptr, evJoin = nullptr;
    if (!sQ) {
        cudaStreamCreateWithFlags(&sQ, cudaStreamNonBlocking);
        cudaEventCreateWithFlags(&evFork, cudaEventDisableTiming);
        cudaEventCreateWithFlags(&evJoin, cudaEventDisableTiming);
    }

    auto G_N = mma_gemm_kernel<false, false, true, false>;   // -> fp32
    auto G_R = mma_gemm_kernel<true, false, false, true>;    // relu -> split
    auto G_E = mma_gemm_kernel<false, true, true, false>;    // +resid -> fp32
    cudaFuncSetAttribute(G_N, cudaFuncAttributeMaxDynamicSharedMemorySize, SMEM_BYTES);
    cudaFuncSetAttribute(G_R, cudaFuncAttributeMaxDynamicSharedMemorySize, SMEM_BYTES);
    cudaFuncSetAttribute(G_E, cudaFuncAttributeMaxDynamicSharedMemorySize, SMEM_BYTES);
    cudaFuncSetAttribute(scatter_mma_kernel,
                         cudaFuncAttributeMaxDynamicSharedMemorySize, SMEM_BYTES);

    const int mb = (M + 127) / 128;
    const dim3 gsm(CAP / 128, 26);
    const dim3 gs16(CAP / 16, 26);
    const int CT = 256;

    // ---- shared prologue (main stream) ----
    zero_cnt_kernel<<<1, 32>>>();
    compact_kernel<<<(27 * M + 255) / 256, 256>>>(nbr, M);
    cudaEventRecord(evFork, 0);

    // ---- cond branch on forked stream: conv_Q + MLP -> qd ----
    cudaStreamWaitEvent(sQ, evFork, 0);
    convert_w_kernel<<<(64 * 128 + CT - 1) / CT, CT, 0, sQ>>>(WQ2, wt + OFF_WQ2, 64, 128);
    convert_w_kernel<<<(128 * 256 + CT - 1) / CT, CT, 0, sQ>>>(WQ3, wt + OFF_WQ3, 128, 256);
    convert_w_kernel<<<(256 * 256 + CT - 1) / CT, CT, 0, sQ>>>(WQ4, wt + OFF_WQ4, 256, 256);
    gemm_kernel<128, 64, 16, 8, 8, false, false, false><<<dim3(mb, 1), 128, 0, sQ>>>(cond, WQ1 + 13 * 16 * 64, bQ1, nullptr, qa, M, 16, 64);
    scatter_kernel<16, 64, 16, false><<<gs16, 64, 0, sQ>>>(cond, WQ1, qa);
    convert_act_kernel<true><<<(M * 16 + CT - 1) / CT, CT, 0, sQ>>>(qa, act2, M, 64);
    G_R<<<dim3(mb, 1), 128, SMEM_BYTES, sQ>>>(act2, wt + OFF_WQ2, bQ2, nullptr, nullptr, act3, M, 64, 128);
    G_R<<<dim3(mb, 2), 128, SMEM_BYTES, sQ>>>(act3, wt + OFF_WQ3, bQ3, nullptr, nullptr, act2, M, 128, 256);
    G_N<<<dim3(mb, 2), 128, SMEM_BYTES, sQ>>>(act2, wt + OFF_WQ4, bQ4, nullptr, qd, nullptr, M, 256, 256);
    cudaEventRecord(evJoin, sQ);

    // ---- conv chain on main stream ----
    convert_w27x4_kernel<<<(4 * 27 * 16384 + CT - 1) / CT, CT>>>(W1a, W1b, W2a, W2b, w27);
    convert_act_kernel<false><<<(M * 32 + CT - 1) / CT, CT>>>(x, act0, M, 128);

    // conv_1a: t1 = x @ W1a[13] + b1a ; += taps
    G_N<<<dim3(mb, 1), 128, SMEM_BYTES>>>(act0, w27 + W27_1A + 13 * 32768, b1a, nullptr, t1, nullptr, M, 128, 128);
    scatter_mma_kernel<<<gsm, 128, SMEM_BYTES>>>(act0, w27 + W27_1A, t1);

    // conv_1b: t2 = relu(t1) @ W1b + b1b ; += taps
    convert_act_kernel<true><<<(M * 32 + CT - 1) / CT, CT>>>(t1, act1, M, 128);
    G_N<<<dim3(mb, 1), 128, SMEM_BYTES>>>(act1, w27 + W27_1B + 13 * 32768, b1b, nullptr, t2, nullptr, M, 128, 128);
    scatter_mma_kernel<<<gsm, 128, SMEM_BYTES>>>(act1, w27 + W27_1B, t2);

    // join cond branch, FiLM: act1 = split(t2*beta+gamma)
    cudaStreamWaitEvent(0, evJoin, 0);
    film_convert_kernel<<<(M * 32 + CT - 1) / CT, CT>>>(t2, qd, act1, M);

    // conv_2a: t1 = film @ W2a + b2a ; += taps
    G_N<<<dim3(mb, 1), 128, SMEM_BYTES>>>(act1, w27 + W27_2A + 13 * 32768, b2a, nullptr, t1, nullptr, M, 128, 128);
    scatter_mma_kernel<<<gsm, 128, SMEM_BYTES>>>(act1, w27 + W27_2A, t1);

    // conv_2b + residual: out = relu(t1) @ W2b + b2b + x ; += taps
    convert_act_kernel<true><<<(M * 32 + CT - 1) / CT, CT>>>(t1, act0, M, 128);
    G_E<<<dim3(mb, 1), 128, SMEM_BYTES>>>(act0, w27 + W27_2B + 13 * 32768, b2b, x, out, nullptr, M, 128, 128);
    scatter_mma_kernel<<<gsm, 128, SMEM_BYTES>>>(act0, w27 + W27_2B, out);
}

// round 11
// speedup vs baseline: 1.0065x; 1.0065x over previous
#include <cuda_runtime.h>
#include <cuda_bf16.h>
#include <cstdint>
#include <math.h>

#define MAXM 100000
#define MPAD 100096          // 782*128, covers last GEMM tile rows
#define CAP  4096

// ---------------- scratch (device globals; no allocations allowed) ----------
__device__ int   g_cnt[27];
__device__ int   g_pairM[27 * CAP];
__device__ int   g_pairS[27 * CAP];
// fp32 scratch: t1(M*128) t2(M*128) qa(M*64) qd(M*256) = M*576 floats
__device__ float g_buf[(size_t)MAXM * 576];
// bf16 [hi|lo] activation buffers (conv chain: act0/act1 ; cond chain: act2/act3)
__device__ __nv_bfloat16 g_act0[(size_t)MPAD * 512];
__device__ __nv_bfloat16 g_act1[(size_t)MPAD * 512];
__device__ __nv_bfloat16 g_act2[(size_t)MPAD * 512];
__device__ __nv_bfloat16 g_act3[(size_t)MPAD * 512];
// bf16 [hi|lo] transposed 27-tap conv weights: [27][N=128][2K=256] per conv
__device__ __nv_bfloat16 g_w27[4 * 27 * 32768];
#define W27_1A 0
#define W27_1B (27 * 32768)
#define W27_2A (2 * 27 * 32768)
#define W27_2B (3 * 27 * 32768)
// bf16 [hi|lo] transposed MLP weights [N][2K]
__device__ __nv_bfloat16 g_wt[16384 + 65536 + 131072];
#define OFF_WQ2 0
#define OFF_WQ3 16384
#define OFF_WQ4 (16384 + 65536)

__device__ __forceinline__ uint32_t smem_to_u32(const void* p) {
    uint32_t a;
    asm("{ .reg .u64 t; cvta.to.shared.u64 t, %1; cvt.u32.u64 %0, t; }" : "=r"(a) : "l"(p));
    return a;
}
__device__ __forceinline__ uint32_t sw128(uint32_t b) { return b ^ ((b >> 3) & 0x70); }

// ---------------- neighbor compaction ---------------------------------------
__global__ void zero_cnt_kernel() {
    if (threadIdx.x < 27) g_cnt[threadIdx.x] = 0;
}
__global__ void compact_kernel(const int* __restrict__ nbr, int Mrows) {
    int idx = blockIdx.x * blockDim.x + threadIdx.x;
    if (idx >= 27 * Mrows) return;
    int k = idx / Mrows;
    if (k == 13) return;
    int s = nbr[idx];
    if (s >= 0) {
        int m = idx - k * Mrows;
        int pos = atomicAdd(&g_cnt[k], 1);
        if (pos < CAP) { g_pairM[k * CAP + pos] = m; g_pairS[k * CAP + pos] = s; }
    }
}

// ---------------- fp32 -> bf16 hi/lo conversions -----------------------------
__device__ __forceinline__ void split_bf16(float v, __nv_bfloat16& h, __nv_bfloat16& l) {
    h = __float2bfloat16(v);
    l = __float2bfloat16(v - __bfloat162float(h));
}
template <bool RELU>
__global__ void convert_act_kernel(const float* __restrict__ src,
                                   __nv_bfloat16* __restrict__ dst, int Mrows, int K) {
    int idx = blockIdx.x * blockDim.x + threadIdx.x;
    int total = Mrows * (K / 4);
    if (idx >= total) return;
    int m  = idx / (K / 4);
    int k4 = (idx % (K / 4)) * 4;
    float4 v = *reinterpret_cast<const float4*>(src + (size_t)m * K + k4);
    if (RELU) {
        v.x = fmaxf(v.x, 0.f); v.y = fmaxf(v.y, 0.f);
        v.z = fmaxf(v.z, 0.f); v.w = fmaxf(v.w, 0.f);
    }
    __nv_bfloat16 h[4], l[4];
    split_bf16(v.x, h[0], l[0]); split_bf16(v.y, h[1], l[1]);
    split_bf16(v.z, h[2], l[2]); split_bf16(v.w, h[3], l[3]);
    __nv_bfloat16* dh = dst + (size_t)m * 2 * K + k4;
    *reinterpret_cast<__nv_bfloat162*>(dh)     = __nv_bfloat162(h[0], h[1]);
    *reinterpret_cast<__nv_bfloat162*>(dh + 2) = __nv_bfloat162(h[2], h[3]);
    __nv_bfloat16* dl = dh + K;
    *reinterpret_cast<__nv_bfloat162*>(dl)     = __nv_bfloat162(l[0], l[1]);
    *reinterpret_cast<__nv_bfloat162*>(dl + 2) = __nv_bfloat162(l[2], l[3]);
}
// W [K,N] fp32 -> dst [N][2K] bf16 (hi | lo), transposed
__global__ void convert_w_kernel(const float* __restrict__ W,
                                 __nv_bfloat16* __restrict__ dst, int K, int N) {
    int idx = blockIdx.x * blockDim.x + threadIdx.x;
    if (idx >= K * N) return;
    int k = idx / N, n = idx % N;
    __nv_bfloat16 h, l;
    split_bf16(W[idx], h, l);
    dst[(size_t)n * 2 * K + k]     = h;
    dst[(size_t)n * 2 * K + K + k] = l;
}
// all 27 taps of all 4 convs in one kernel
__global__ void convert_w27x4_kernel(const float* __restrict__ Wa, const float* __restrict__ Wb,
                                     const float* __restrict__ Wc, const float* __restrict__ Wd,
                                     __nv_bfloat16* __restrict__ dst) {
    int idx = blockIdx.x * blockDim.x + threadIdx.x;
    if (idx >= 4 * 27 * 16384) return;
    int conv = idx / (27 * 16384);
    int rem  = idx % (27 * 16384);
    const float* W = (conv == 0) ? Wa : (conv == 1) ? Wb : (conv == 2) ? Wc : Wd;
    int k = rem >> 14;
    int r = (rem >> 7) & 127;   // K index
    int n = rem & 127;          // N index
    __nv_bfloat16 h, l;
    split_bf16(W[rem], h, l);
    __nv_bfloat16* d = dst + (size_t)conv * 27 * 32768 + (size_t)k * 32768 + n * 256;
    d[r]       = h;
    d[128 + r] = l;
}
// FiLM + conversion: dst = bf16 split of (t2*beta+gamma), K=128
__global__ void film_convert_kernel(const float* __restrict__ t2, const float* __restrict__ qd,
                                    __nv_bfloat16* __restrict__ dst, int Mrows) {
    int idx = blockIdx.x * blockDim.x + threadIdx.x;
    if (idx >= Mrows * 32) return;
    int m  = idx / 32;
    int c4 = (idx % 32) * 4;
    float4 t = *reinterpret_cast<const float4*>(t2 + (size_t)m * 128 + c4);
    float4 b = *reinterpret_cast<const float4*>(qd + (size_t)m * 256 + c4);
    float4 g = *reinterpret_cast<const float4*>(qd + (size_t)m * 256 + 128 + c4);
    float4 o;
    o.x = fmaf(t.x, b.x, g.x); o.y = fmaf(t.y, b.y, g.y);
    o.z = fmaf(t.z, b.z, g.z); o.w = fmaf(t.w, b.w, g.w);
    __nv_bfloat16 h[4], l[4];
    split_bf16(o.x, h[0], l[0]); split_bf16(o.y, h[1], l[1]);
    split_bf16(o.z, h[2], l[2]); split_bf16(o.w, h[3], l[3]);
    __nv_bfloat16* dh = dst + (size_t)m * 256 + c4;
    *reinterpret_cast<__nv_bfloat162*>(dh)     = __nv_bfloat162(h[0], h[1]);
    *reinterpret_cast<__nv_bfloat162*>(dh + 2) = __nv_bfloat162(h[2], h[3]);
    __nv_bfloat16* dl = dh + 128;
    *reinterpret_cast<__nv_bfloat162*>(dl)     = __nv_bfloat162(l[0], l[1]);
    *reinterpret_cast<__nv_bfloat162*>(dl + 2) = __nv_bfloat162(l[2], l[3]);
}

// ================= mma.sync primitives =======================================
#define SMEM_BYTES 98304   // 3 stages x (16KB A + 16KB B)

__device__ __forceinline__ void cp_async16(uint32_t dst, const void* src) {
    asm volatile("cp.async.cg.shared.global [%0], [%1], 16;" :: "r"(dst), "l"(src));
}
__device__ __forceinline__ void cp_commit() {
    asm volatile("cp.async.commit_group;");
}
__device__ __forceinline__ void ldm_x4(uint32_t a, uint32_t& r0, uint32_t& r1,
                                       uint32_t& r2, uint32_t& r3) {
    asm volatile("ldmatrix.sync.aligned.m8n8.x4.shared.b16 {%0,%1,%2,%3}, [%4];"
                 : "=r"(r0), "=r"(r1), "=r"(r2), "=r"(r3) : "r"(a));
}
__device__ __forceinline__ void mma16816(float* c, const uint32_t* a, const uint32_t* b) {
    asm volatile("mma.sync.aligned.m16n8k16.row.col.f32.bf16.bf16.f32 "
                 "{%0,%1,%2,%3}, {%4,%5,%6,%7}, {%8,%9}, {%0,%1,%2,%3};"
                 : "+f"(c[0]), "+f"(c[1]), "+f"(c[2]), "+f"(c[3])
                 : "r"(a[0]), "r"(a[1]), "r"(a[2]), "r"(a[3]), "r"(b[0]), "r"(b[1]));
}

// ================= dense GEMM: 128x128 tile, 4 warps x 64x64, 3-stage pipe ===
template <bool RELU_OUT, bool RESID, bool WF32, bool WBF16>
__global__ void __launch_bounds__(128, 2)
mma_gemm_kernel(const __nv_bfloat16* __restrict__ Act,
                const __nv_bfloat16* __restrict__ Wt,
                const float* __restrict__ bias, const float* __restrict__ resid,
                float* __restrict__ C, __nv_bfloat16* __restrict__ ActOut,
                int Mrows, int K, int Ntot)
{
    extern __shared__ __align__(1024) char smem[];
    const uint32_t sbase = smem_to_u32(smem);

    const int tid  = threadIdx.x;
    const int lane = tid & 31;
    const int wid  = tid >> 5;          // 0..3
    const int wm   = wid >> 1;          // 0..1 (64-row slab)
    const int wn   = wid & 1;           // 0..1 (64-col slab)
    const int row0 = blockIdx.x * 128;
    const int n0   = blockIdx.y * 128;
    const size_t strideA = 2 * (size_t)K;

    float acc[4][8][4];
#pragma unroll
    for (int mi = 0; mi < 4; mi++)
#pragma unroll
        for (int ni = 0; ni < 8; ni++)
#pragma unroll
            for (int j = 0; j < 4; j++) acc[mi][ni][j] = 0.f;

    const int kc64 = K / 64;
    const int nch  = 3 * kc64;

    auto load_stage = [&](int c, int stage) {
        const int seg = c / kc64;
        const int kk  = (c % kc64) * 64;
        const int Ak  = kk + (seg == 1 ? K : 0);
        const int Bk  = kk + (seg == 2 ? K : 0);
        const uint32_t sA = sbase + stage * 32768u;
        const uint32_t sB = sA + 16384u;
#pragma unroll
        for (int it = 0; it < 8; it++) {
            int i  = tid + it * 128;          // 0..1023
            int r  = i >> 3;
            int c16 = i & 7;
            cp_async16(sA + sw128(r * 128 + c16 * 16),
                       Act + (size_t)(row0 + r) * strideA + Ak + c16 * 8);
            cp_async16(sB + sw128(r * 128 + c16 * 16),
                       Wt + (size_t)(n0 + r) * strideA + Bk + c16 * 8);
        }
        cp_commit();
    };

    load_stage(0, 0);
    load_stage(1, 1);
    int nextld = 2;
    for (int c = 0; c < nch; c++) {
        const int cur = c % 3;
        if (c + 1 < nch) asm volatile("cp.async.wait_group 1;");
        else             asm volatile("cp.async.wait_group 0;");
        __syncthreads();
        if (nextld < nch) { load_stage(nextld, nextld % 3); nextld++; }

        const uint32_t sA = sbase + cur * 32768u;
        const uint32_t sB = sA + 16384u;
#pragma unroll
        for (int kk = 0; kk < 4; kk++) {
            uint32_t af[4][4];
#pragma unroll
            for (int mi = 0; mi < 4; mi++) {
                int r = wm * 64 + mi * 16 + (lane & 15);
                uint32_t a = sA + sw128((uint32_t)(r * 128 + kk * 32 + (lane >> 4) * 16));
                ldm_x4(a, af[mi][0], af[mi][1], af[mi][2], af[mi][3]);
            }
            uint32_t bf[8][2];
#pragma unroll
            for (int nj = 0; nj < 4; nj++) {
                int g = lane >> 3;
                int nr = wn * 64 + nj * 16 + (g >> 1) * 8 + (lane & 7);
                uint32_t a = sB + sw128((uint32_t)(nr * 128 + kk * 32 + (g & 1) * 16));
                uint32_t r0, r1, r2, r3;
                ldm_x4(a, r0, r1, r2, r3);
                bf[nj * 2][0] = r0; bf[nj * 2][1] = r1;
                bf[nj * 2 + 1][0] = r2; bf[nj * 2 + 1][1] = r3;
            }
#pragma unroll
            for (int mi = 0; mi < 4; mi++)
#pragma unroll
                for (int ni = 0; ni < 8; ni++)
                    mma16816(acc[mi][ni], af[mi], bf[ni]);
        }
    }
    __syncthreads();

    const int tg  = lane >> 2;
    const int tc2 = (lane & 3) * 2;
#pragma unroll
    for (int mi = 0; mi < 4; mi++) {
#pragma unroll
        for (int half = 0; half < 2; half++) {
            const int gr = row0 + wm * 64 + mi * 16 + tg + half * 8;
            if (gr >= Mrows) continue;
#pragma unroll
            for (int ni = 0; ni < 8; ni++) {
                const int gc = n0 + wn * 64 + ni * 8 + tc2;
                float2 o;
                o.x = acc[mi][ni][half * 2 + 0];
                o.y = acc[mi][ni][half * 2 + 1];
                float2 bv = *reinterpret_cast<const float2*>(bias + gc);
                o.x += bv.x; o.y += bv.y;
                if (RESID) {
                    float2 rv = *reinterpret_cast<const float2*>(resid + (size_t)gr * Ntot + gc);
                    o.x += rv.x; o.y += rv.y;
                }
                if (RELU_OUT) { o.x = fmaxf(o.x, 0.f); o.y = fmaxf(o.y, 0.f); }
                if (WF32)
                    *reinterpret_cast<float2*>(C + (size_t)gr * Ntot + gc) = o;
                if (WBF16) {
                    __nv_bfloat16 h0, l0, h1, l1;
                    split_bf16(o.x, h0, l0);
                    split_bf16(o.y, h1, l1);
                    *reinterpret_cast<__nv_bfloat162*>(ActOut + (size_t)gr * 2 * Ntot + gc)
                        = __nv_bfloat162(h0, h1);
                    *reinterpret_cast<__nv_bfloat162*>(ActOut + (size_t)gr * 2 * Ntot + Ntot + gc)
                        = __nv_bfloat162(l0, l1);
                }
            }
        }
    }
}

// ============ MMA scatter: Out[dst[p]] += Act[src[p]] @ W27[k]^T =============
// 4 warps x 64x64 warp tiles, 3-stage pipeline, occ 2
__global__ void __launch_bounds__(128, 2)
scatter_mma_kernel(const __nv_bfloat16* __restrict__ Act,
                   const __nv_bfloat16* __restrict__ W27,
                   float* __restrict__ Out)
{
    extern __shared__ __align__(1024) char smem[];
    __shared__ int srow[128];
    __shared__ int drow[128];
    const uint32_t sbase = smem_to_u32(smem);

    int kk = blockIdx.y;
    if (kk >= 13) kk++;
    const int cnt = g_cnt[kk];
    const int p0  = blockIdx.x * 128;
    if (p0 >= cnt) return;
    const int np = min(128, cnt - p0);

    const int tid  = threadIdx.x;
    const int lane = tid & 31;
    const int wid  = tid >> 5;          // 0..3
    const int wm   = wid >> 1;          // 0..1
    const int wn   = wid & 1;           // 0..1

    {
        int p = p0 + min(tid, np - 1);
        srow[tid] = g_pairS[kk * CAP + p];
        drow[tid] = (tid < np) ? g_pairM[kk * CAP + p] : -1;
    }
    __syncthreads();

    const __nv_bfloat16* Wt = W27 + (size_t)kk * 32768;

    float acc[4][8][4];
#pragma unroll
    for (int mi = 0; mi < 4; mi++)
#pragma unroll
        for (int ni = 0; ni < 8; ni++)
#pragma unroll
            for (int j = 0; j < 4; j++) acc[mi][ni][j] = 0.f;

    auto load_stage = [&](int c, int stage) {
        const int seg = c >> 1;
        const int kk64 = (c & 1) * 64;
        const int Ak  = kk64 + (seg == 1 ? 128 : 0);
        const int Bk  = kk64 + (seg == 2 ? 128 : 0);
        const uint32_t sA = sbase + stage * 32768u;
        const uint32_t sB = sA + 16384u;
#pragma unroll
        for (int it = 0; it < 8; it++) {
            int i  = tid + it * 128;
            int r  = i >> 3;
            int c16 = i & 7;
            cp_async16(sA + sw128(r * 128 + c16 * 16),
                       Act + (size_t)srow[r] * 256 + Ak + c16 * 8);
            cp_async16(sB + sw128(r * 128 + c16 * 16),
                       Wt + (size_t)r * 256 + Bk + c16 * 8);
        }
        cp_commit();
    };

    load_stage(0, 0);
    load_stage(1, 1);
    int nextld = 2;
    for (int c = 0; c < 6; c++) {
        const int cur = c % 3;
        if (c + 1 < 6) asm volatile("cp.async.wait_group 1;");
        else           asm volatile("cp.async.wait_group 0;");
        __syncthreads();
        if (nextld < 6) { load_stage(nextld, nextld % 3); nextld++; }

        const uint32_t sA = sbase + cur * 32768u;
        const uint32_t sB = sA + 16384u;
#pragma unroll
        for (int kq = 0; kq < 4; kq++) {
            uint32_t af[4][4];
#pragma unroll
            for (int mi = 0; mi < 4; mi++) {
                int r = wm * 64 + mi * 16 + (lane & 15);
                uint32_t a = sA + sw128((uint32_t)(r * 128 + kq * 32 + (lane >> 4) * 16));
                ldm_x4(a, af[mi][0], af[mi][1], af[mi][2], af[mi][3]);
            }
            uint32_t bf[8][2];
#pragma unroll
            for (int nj = 0; nj < 4; nj++) {
                int g = lane >> 3;
                int nr = wn * 64 + nj * 16 + (g >> 1) * 8 + (lane & 7);
                uint32_t a = sB + sw128((uint32_t)(nr * 128 + kq * 32 + (g & 1) * 16));
                uint32_t r0, r1, r2, r3;
                ldm_x4(a, r0, r1, r2, r3);
                bf[nj * 2][0] = r0; bf[nj * 2][1] = r1;
                bf[nj * 2 + 1][0] = r2; bf[nj * 2 + 1][1] = r3;
            }
#pragma unroll
            for (int mi = 0; mi < 4; mi++)
#pragma unroll
                for (int ni = 0; ni < 8; ni++)
                    mma16816(acc[mi][ni], af[mi], bf[ni]);
        }
    }

    const int tg  = lane >> 2;
    const int tc2 = (lane & 3) * 2;
#pragma unroll
    for (int mi = 0; mi < 4; mi++) {
#pragma unroll
        for (int half = 0; half < 2; half++) {
            const int rl = wm * 64 + mi * 16 + tg + half * 8;
            const int gr = drow[rl];
            if (gr < 0) continue;
            float* Orow = Out + (size_t)gr * 128;
#pragma unroll
            for (int ni = 0; ni < 8; ni++) {
                const int gc = wn * 64 + ni * 8 + tc2;
                atomicAdd(Orow + gc,     acc[mi][ni][half * 2 + 0]);
                atomicAdd(Orow + gc + 1, acc[mi][ni][half * 2 + 1]);
            }
        }
    }
}

// ---------------- SIMT GEMM (tiny K=16 cond conv) ----------------------------
template <int BM, int BN, int BK, int TM, int TN, bool RELU_A, bool RELU_OUT, bool RESID>
__global__ void __launch_bounds__((BM / TM) * (BN / TN))
gemm_kernel(const float* __restrict__ A, const float* __restrict__ B,
            const float* __restrict__ bias, const float* __restrict__ resid,
            float* __restrict__ C, int Mrows, int Kdim, int Ndim)
{
    constexpr int NT = (BM / TM) * (BN / TN);
    __shared__ float As[BK][BM];
    __shared__ float Bs[BK][BN];
    const int tid  = threadIdx.x;
    const int row0 = blockIdx.x * BM;
    const int col0 = blockIdx.y * BN;
    const int tr   = tid / (BN / TN);
    const int tc   = tid % (BN / TN);
    float acc[TM][TN];
#pragma unroll
    for (int i = 0; i < TM; i++)
#pragma unroll
        for (int j = 0; j < TN; j++) acc[i][j] = 0.f;
    for (int k0 = 0; k0 < Kdim; k0 += BK) {
        for (int i = tid * 4; i < BM * BK; i += NT * 4) {
            int r = i / BK, kk = i % BK;
            float4 v = make_float4(0.f, 0.f, 0.f, 0.f);
            int grr = row0 + r;
            if (grr < Mrows)
                v = *reinterpret_cast<const float4*>(A + (size_t)grr * Kdim + k0 + kk);
            if (RELU_A) {
                v.x = fmaxf(v.x, 0.f); v.y = fmaxf(v.y, 0.f);
                v.z = fmaxf(v.z, 0.f); v.w = fmaxf(v.w, 0.f);
            }
            As[kk + 0][r] = v.x; As[kk + 1][r] = v.y;
            As[kk + 2][r] = v.z; As[kk + 3][r] = v.w;
        }
        for (int i = tid * 4; i < BK * BN; i += NT * 4) {
            int r = i / BN, c = i % BN;
            *reinterpret_cast<float4*>(&Bs[r][c]) =
                *reinterpret_cast<const float4*>(B + (size_t)(k0 + r) * Ndim + col0 + c);
        }
        __syncthreads();
#pragma unroll
        for (int kk = 0; kk < BK; kk++) {
            float af[TM], bf2[TN];
#pragma unroll
            for (int i = 0; i < TM; i++) af[i] = As[kk][tr * TM + i];
#pragma unroll
            for (int j = 0; j < TN; j++) bf2[j] = Bs[kk][tc * TN + j];
#pragma unroll
            for (int i = 0; i < TM; i++)
#pragma unroll
                for (int j = 0; j < TN; j++) acc[i][j] = fmaf(af[i], bf2[j], acc[i][j]);
        }
        __syncthreads();
    }
#pragma unroll
    for (int i = 0; i < TM; i++) {
        int grr = row0 + tr * TM + i;
        if (grr >= Mrows) continue;
        float* Crow = C + (size_t)grr * Ndim + col0 + tc * TN;
#pragma unroll
        for (int j = 0; j < TN; j += 4) {
            int gc = col0 + tc * TN + j;
            float4 bv = *reinterpret_cast<const float4*>(bias + gc);
            float4 o;
            o.x = acc[i][j + 0] + bv.x; o.y = acc[i][j + 1] + bv.y;
            o.z = acc[i][j + 2] + bv.z; o.w = acc[i][j + 3] + bv.w;
            if (RESID) {
                float4 rv = *reinterpret_cast<const float4*>(resid + (size_t)grr * Ndim + gc);
                o.x += rv.x; o.y += rv.y; o.z += rv.z; o.w += rv.w;
            }
            if (RELU_OUT) {
                o.x = fmaxf(o.x, 0.f); o.y = fmaxf(o.y, 0.f);
                o.z = fmaxf(o.z, 0.f); o.w = fmaxf(o.w, 0.f);
            }
            *reinterpret_cast<float4*>(Crow + j) = o;
        }
    }
}

// ---------------- SIMT scatter (tiny cond conv taps, Ci=16) ------------------
template <int Ci, int Co, int PB, bool RELU_A>
__global__ void __launch_bounds__(Co)
scatter_kernel(const float* __restrict__ F, const float* __restrict__ W,
               float* __restrict__ Out)
{
    int kk = blockIdx.y;
    if (kk >= 13) kk++;
    const int cnt = g_cnt[kk];
    const int p0  = blockIdx.x * PB;
    if (p0 >= cnt) return;
    const int np = min(PB, cnt - p0);
    __shared__ float gsh[PB][Ci];
    __shared__ int   mout[PB];
    const int tid = threadIdx.x;
    for (int i = tid; i < PB * Ci; i += Co) {
        int p = i / Ci, c = i % Ci;
        float v = 0.f;
        if (p < np) {
            int ms = g_pairS[kk * CAP + p0 + p];
            v = F[(size_t)ms * Ci + c];
            if (RELU_A) v = fmaxf(v, 0.f);
        }
        gsh[p][c] = v;
    }
    if (tid < PB) mout[tid] = (tid < np) ? g_pairM[kk * CAP + p0 + tid] : 0;
    __syncthreads();
    float acc[PB];
#pragma unroll
    for (int p = 0; p < PB; p++) acc[p] = 0.f;
    const float* Wk = W + (size_t)kk * Ci * Co + tid;
#pragma unroll 4
    for (int i = 0; i < Ci; i++) {
        float wv = Wk[(size_t)i * Co];
#pragma unroll
        for (int p = 0; p < PB; p++) acc[p] = fmaf(gsh[p][i], wv, acc[p]);
    }
    for (int p = 0; p < np; p++)
        atomicAdd(&Out[(size_t)mout[p] * Co + tid], acc[p]);
}

// ---------------- launch -----------------------------------------------------
extern "C" void kernel_launch(void* const* d_in, const int* in_sizes, int n_in,
                              void* d_out, int out_size)
{
    const float* x    = (const float*)d_in[0];
    const float* cond = (const float*)d_in[1];
    const float* W1a  = (const float*)d_in[2];   const float* b1a = (const float*)d_in[3];
    const float* W1b  = (const float*)d_in[4];   const float* b1b = (const float*)d_in[5];
    const float* W2a  = (const float*)d_in[6];   const float* b2a = (const float*)d_in[7];
    const float* W2b  = (const float*)d_in[8];   const float* b2b = (const float*)d_in[9];
    const float* WQ1  = (const float*)d_in[10];  const float* bQ1 = (const float*)d_in[11];
    const float* WQ2  = (const float*)d_in[12];  const float* bQ2 = (const float*)d_in[13];
    const float* WQ3  = (const float*)d_in[14];  const float* bQ3 = (const float*)d_in[15];
    const float* WQ4  = (const float*)d_in[16];  const float* bQ4 = (const float*)d_in[17];
    const int*   nbr  = (const int*)d_in[18];
    float* out = (float*)d_out;

    const int M = in_sizes[0] / 128;

    float* buf = nullptr;           cudaGetSymbolAddress((void**)&buf, g_buf);
    __nv_bfloat16* act0 = nullptr;  cudaGetSymbolAddress((void**)&act0, g_act0);
    __nv_bfloat16* act1 = nullptr;  cudaGetSymbolAddress((void**)&act1, g_act1);
    __nv_bfloat16* act2 = nullptr;  cudaGetSymbolAddress((void**)&act2, g_act2);
    __nv_bfloat16* act3 = nullptr;  cudaGetSymbolAddress((void**)&act3, g_act3);
    __nv_bfloat16* w27 = nullptr;   cudaGetSymbolAddress((void**)&w27, g_w27);
    __nv_bfloat16* wt = nullptr;    cudaGetSymbolAddress((void**)&wt, g_wt);

    float* t1 = buf;                            // M*128
    float* t2 = t1 + (size_t)MAXM * 128;        // M*128
    float* qa = t2 + (size_t)MAXM * 128;        // M*64
    float* qd = qa + (size_t)MAXM * 64;         // M*256

    // static fork/join machinery (created on first, non-capture call)
    static cudaStream_t sQ = nullptr;
    static cudaEvent_t evFork = nullptr, evJoin = nullptr;
    if (!sQ) {
        cudaStreamCreateWithFlags(&sQ, cudaStreamNonBlocking);
        cudaEventCreateWithFlags(&evFork, cudaEventDisableTiming);
        cudaEventCreateWithFlags(&evJoin, cudaEventDisableTiming);
    }

    auto G_N = mma_gemm_kernel<false, false, true, false>;   // -> fp32
    auto G_R = mma_gemm_kernel<true, false, false, true>;    // relu -> split
    auto G_E = mma_gemm_kernel<false, true, true, false>;    // +resid -> fp32
    cudaFuncSetAttribute(G_N, cudaFuncAttributeMaxDynamicSharedMemorySize, SMEM_BYTES);
    cudaFuncSetAttribute(G_R, cudaFuncAttributeMaxDynamicSharedMemorySize, SMEM_BYTES);
    cudaFuncSetAttribute(G_E, cudaFuncAttributeMaxDynamicSharedMemorySize, SMEM_BYTES);
    cudaFuncSetAttribute(scatter_mma_kernel,
                         cudaFuncAttributeMaxDynamicSharedMemorySize, SMEM_BYTES);

    const int mb = (M + 127) / 128;
    const dim3 gsm(CAP / 128, 26);
    const dim3 gs16(CAP / 16, 26);
    const int CT = 256;

    // ---- shared prologue (main stream) ----
    zero_cnt_kernel<<<1, 32>>>();
    compact_kernel<<<(27 * M + 255) / 256, 256>>>(nbr, M);
    cudaEventRecord(evFork, 0);

    // ---- cond branch on forked stream: conv_Q + MLP -> qd ----
    cudaStreamWaitEvent(sQ, evFork, 0);
    convert_w_kernel<<<(64 * 128 + CT - 1) / CT, CT, 0, sQ>>>(WQ2, wt + OFF_WQ2, 64, 128);
    convert_w_kernel<<<(128 * 256 + CT - 1) / CT, CT, 0, sQ>>>(WQ3, wt + OFF_WQ3, 128, 256);
    convert_w_kernel<<<(256 * 256 + CT - 1) / CT, CT, 0, sQ>>>(WQ4, wt + OFF_WQ4, 256, 256);
    gemm_kernel<128, 64, 16, 8, 8, false, false, false><<<dim3(mb, 1), 128, 0, sQ>>>(cond, WQ1 + 13 * 16 * 64, bQ1, nullptr, qa, M, 16, 64);
    scatter_kernel<16, 64, 16, false><<<gs16, 64, 0, sQ>>>(cond, WQ1, qa);
    convert_act_kernel<true><<<(M * 16 + CT - 1) / CT, CT, 0, sQ>>>(qa, act2, M, 64);
    G_R<<<dim3(mb, 1), 128, SMEM_BYTES, sQ>>>(act2, wt + OFF_WQ2, bQ2, nullptr, nullptr, act3, M, 64, 128);
    G_R<<<dim3(mb, 2), 128, SMEM_BYTES, sQ>>>(act3, wt + OFF_WQ3, bQ3, nullptr, nullptr, act2, M, 128, 256);
    G_N<<<dim3(mb, 2), 128, SMEM_BYTES, sQ>>>(act2, wt + OFF_WQ4, bQ4, nullptr, qd, nullptr, M, 256, 256);
    cudaEventRecord(evJoin, sQ);

    // ---- conv chain on main stream ----
    convert_w27x4_kernel<<<(4 * 27 * 16384 + CT - 1) / CT, CT>>>(W1a, W1b, W2a, W2b, w27);
    convert_act_kernel<false><<<(M * 32 + CT - 1) / CT, CT>>>(x, act0, M, 128);

    // conv_1a: t1 = x @ W1a[13] + b1a ; += taps
    G_N<<<dim3(mb, 1), 128, SMEM_BYTES>>>(act0, w27 + W27_1A + 13 * 32768, b1a, nullptr, t1, nullptr, M, 128, 128);
    scatter_mma_kernel<<<gsm, 128, SMEM_BYTES>>>(act0, w27 + W27_1A, t1);

    // conv_1b: t2 = relu(t1) @ W1b + b1b ; += taps
    convert_act_kernel<true><<<(M * 32 + CT - 1) / CT, CT>>>(t1, act1, M, 128);
    G_N<<<dim3(mb, 1), 128, SMEM_BYTES>>>(act1, w27 + W27_1B + 13 * 32768, b1b, nullptr, t2, nullptr, M, 128, 128);
    scatter_mma_kernel<<<gsm, 128, SMEM_BYTES>>>(act1, w27 + W27_1B, t2);

    // join cond branch, FiLM: act1 = split(t2*beta+gamma)
    cudaStreamWaitEvent(0, evJoin, 0);
    film_convert_kernel<<<(M * 32 + CT - 1) / CT, CT>>>(t2, qd, act1, M);

    // conv_2a: t1 = film @ W2a + b2a ; += taps
    G_N<<<dim3(mb, 1), 128, SMEM_BYTES>>>(act1, w27 + W27_2A + 13 * 32768, b2a, nullptr, t1, nullptr, M, 128, 128);
    scatter_mma_kernel<<<gsm, 128, SMEM_BYTES>>>(act1, w27 + W27_2A, t1);

    // conv_2b + residual: out = relu(t1) @ W2b + b2b + x ; += taps
    convert_act_kernel<true><<<(M * 32 + CT - 1) / CT, CT>>>(t1, act0, M, 128);
    G_E<<<dim3(mb, 1), 128, SMEM_BYTES>>>(act0, w27 + W27_2B + 13 * 32768, b2b, x, out, nullptr, M, 128, 128);
    scatter_mma_kernel<<<gsm, 128, SMEM_BYTES>>>(act0, w27 + W27_2B, out);
}